// round 15
// baseline (speedup 1.0000x reference)
#include <cuda_runtime.h>

// Problem constants
#define Bn   2
#define Cc   64
#define Oo   64
#define Gg   16
#define Ee   128
#define Tin  512
#define Wk   7
#define Dd   4
#define Tout 256
#define FO   64
#define PER  264   // padded de-interleaved row length (floats)

// BN-stat partials: [o][j], j = b*32 + d*8 + fh  (64 slots)
__device__ float  g_part1[Oo][64];
__device__ float  g_part2[Oo][64];
__device__ float2 g_ab[Oo];           // {a, bias56}

// ---------------------------------------------------------------------------
// Stats kernel: 256 blocks x 256 threads, each block grid-strides over 4
// chunks (chunk = old (b,c,fh) unit). Low occupancy footprint (<=2 blocks/SM)
// leaves SM slots free so the PDL-launched conv co-resides from t~0.
// Per-chunk body identical to the R8/R14-validated version.
// ---------------------------------------------------------------------------
__global__ __launch_bounds__(256) void stats_kernel(const float* __restrict__ x,
                                                    const float* __restrict__ wgt) {
#if __CUDA_ARCH__ >= 900
    cudaTriggerProgrammaticLaunchCompletion();
#endif
    __shared__ float s_p1[4], s_p2[4];

    const int tid  = threadIdx.x;
    const int warp = tid >> 5;
    const int lane = tid & 31;
    const int sl   = lane & 15;
    const int gidx = lane >> 4;
    const unsigned FULL = 0xffffffffu;

#pragma unroll 1
    for (int q = 0; q < 4; q++) {
        const int cid = blockIdx.x * 4 + q;     // 0..1023
        const int b   = cid >> 9;
        const int c   = (cid >> 3) & 63;
        const int fh  = cid & 7;
        const int f   = fh * 16 + warp * 2 + gidx;

        if (tid < 4) { s_p1[tid] = 0.f; s_p2[tid] = 0.f; }
        __syncthreads();

        const float4* row = reinterpret_cast<const float4*>(
            &x[((b * Cc + c) * Ee + f) * Tin]);

        float4 v[8];
#pragma unroll
        for (int k = 0; k < 8; k++) v[k] = row[sl + 16 * k];

        float se = 0.f, so = 0.f, se2 = 0.f, so2 = 0.f;
#pragma unroll
        for (int k = 0; k < 8; k++) {
            float4 qv = v[k];
            se += qv.x + qv.z;  so += qv.y + qv.w;
            se2 = fmaf(qv.x, qv.x, se2); se2 = fmaf(qv.z, qv.z, se2);
            so2 = fmaf(qv.y, qv.y, so2); so2 = fmaf(qv.w, qv.w, so2);
        }

        const int base = lane & ~15;
        float x0   = __shfl_sync(FULL, v[0].x, base);
        float x1   = __shfl_sync(FULL, v[0].y, base);
        float x509 = __shfl_sync(FULL, v[7].y, base + 15);
        float x510 = __shfl_sync(FULL, v[7].z, base + 15);
        float x511 = __shfl_sync(FULL, v[7].w, base + 15);

#pragma unroll
        for (int off = 1; off < 16; off <<= 1) {
            se  += __shfl_xor_sync(FULL, se,  off);
            so  += __shfl_xor_sync(FULL, so,  off);
            se2 += __shfl_xor_sync(FULL, se2, off);
            so2 += __shfl_xor_sync(FULL, so2, off);
        }

        float c1 = 0.f, c2 = 0.f;
        if (sl < 4) {
            float s1[7], s2[7];
            s1[0] = so - x509 - x511;  s2[0] = so2 - x509 * x509 - x511 * x511;
            s1[1] = se - x510;         s2[1] = se2 - x510 * x510;
            s1[2] = so - x511;         s2[2] = so2 - x511 * x511;
            s1[3] = se;                s2[3] = se2;
            s1[4] = so;                s2[4] = so2;
            s1[5] = se - x0;           s2[5] = se2 - x0 * x0;
            s1[6] = so - x1;           s2[6] = so2 - x1 * x1;

            const int g = c >> 2, d = c & 3;
            const int o = g * 4 + sl;
            const float* wp = &wgt[((o * Dd + d) * Ee + f) * Wk];
#pragma unroll
            for (int w = 0; w < 7; w++) {
                float wv = wp[w];
                c1 = fmaf(wv, s1[w], c1);
                c2 = fmaf(wv * wv, s2[w], c2);
            }
        }
        c1 += __shfl_xor_sync(FULL, c1, 16);
        c2 += __shfl_xor_sync(FULL, c2, 16);
        if (lane < 4) {
            atomicAdd(&s_p1[lane], c1);
            atomicAdd(&s_p2[lane], c2);
        }
        __syncthreads();
        if (tid < 4) {
            const int g = c >> 2, d = c & 3;
            const int j = b * 32 + d * 8 + fh;
            g_part1[g * 4 + tid][j] = s_p1[tid];
            g_part2[g * 4 + tid][j] = s_p2[tid];
        }
        __syncthreads();
    }
}

// ---------------------------------------------------------------------------
// Finalize: 1 block, 64 threads. Triggers at entry (lets conv co-schedule),
// then waits for stats completion before reducing partials.
// ---------------------------------------------------------------------------
__global__ __launch_bounds__(64) void finalize_kernel(const float* __restrict__ gamma,
                                                      const float* __restrict__ beta) {
#if __CUDA_ARCH__ >= 900
    cudaTriggerProgrammaticLaunchCompletion();
    cudaGridDependencySynchronize();
#endif
    const int o = threadIdx.x;
    const float4* p1v = reinterpret_cast<const float4*>(g_part1[o]);
    const float4* p2v = reinterpret_cast<const float4*>(g_part2[o]);
    float p1 = 0.f, p2 = 0.f;
#pragma unroll
    for (int k = 0; k < 16; k++) {
        float4 a = p1v[k], b = p2v[k];
        p1 += (a.x + a.y) + (a.z + a.w);
        p2 += (b.x + b.y) + (b.z + b.w);
    }
    const float M = 1835008.f;   // B*D*E*t*W
    float mean = p1 / M;
    float var  = p2 / M - mean * mean;
    float a    = gamma[o] * rsqrtf(var + 1e-5f);
    g_ab[o] = make_float2(a, 56.f * (beta[o] - mean * a));
}

// ---------------------------------------------------------------------------
// Fused conv + BN-affine + LeakyReLU (validated R5/R6 core). Block = (b,g,fo),
// 2048 blocks, 128 threads. Fill + FMA run before the PDL dependency sync;
// g_ab is read only in the epilogue, after cudaGridDependencySynchronize().
// ---------------------------------------------------------------------------
__global__ __launch_bounds__(128) void conv_kernel(const float* __restrict__ x,
                                                   const float* __restrict__ wgt,
                                                   float* __restrict__ out) {
    __shared__ alignas(16) float pe[8][PER];
    __shared__ alignas(16) float pos_[8][PER];
    __shared__ alignas(16) float ws[8][4][8];   // [w0..w6, 0]

    const int bid  = blockIdx.x;
    const int b    = bid >> 10;
    const int g    = (bid >> 6) & 15;
    const int fo   = bid & 63;
    const int tid  = threadIdx.x;
    const int lane = tid & 31;
    const int warp = tid >> 5;
    const int oc   = lane & 3;
    const int tc   = warp * 8 + (lane >> 2);   // 0..31; outputs t = 8tc..8tc+7

    // zero boundary slots {0,1,258..263} of each pe/pos_ row
    {
        int r  = tid >> 4;
        int s  = tid & 15;
        int ss = s & 7;
        int idx = (ss < 2) ? ss : (256 + ss);
        if (s < 8) pe[r][idx] = 0.f; else pos_[r][idx] = 0.f;
    }

    // de-interleaving fill
#pragma unroll
    for (int k = 0; k < 8; k++) {
        const int c = g * 4 + (k & 3);
        const int f = 2 * fo + (k >> 2);
        float4 v = reinterpret_cast<const float4*>(
            &x[((b * Cc + c) * Ee + f) * Tin])[tid];
        *reinterpret_cast<float2*>(&pe[k][2 * tid + 2])   = make_float2(v.y, v.w);
        *reinterpret_cast<float2*>(&pos_[k][2 * tid + 2]) = make_float2(v.x, v.z);
    }

    // weights
#pragma unroll
    for (int m = 0; m < 2; m++) {
        int j  = tid + 128 * m;
        int r  = j >> 5;
        int o2 = (j >> 3) & 3;
        int w  = j & 7;
        int d  = r & 3;
        int f2 = r >> 2;
        ws[r][o2][w] = (w < 7)
            ? wgt[(((g * 4 + o2) * Dd + d) * Ee + (2 * fo + f2)) * Wk + w] : 0.f;
    }
    __syncthreads();

    float acc[8];
#pragma unroll
    for (int j = 0; j < 8; j++) acc[j] = 0.f;

#pragma unroll
    for (int r = 0; r < 8; r++) {
        const float4* pe4  = reinterpret_cast<const float4*>(pe[r]);
        const float4* pos4 = reinterpret_cast<const float4*>(pos_[r]);
        float E[12], S[12];
        *reinterpret_cast<float4*>(&E[0]) = pe4[2 * tc];
        *reinterpret_cast<float4*>(&E[4]) = pe4[2 * tc + 1];
        *reinterpret_cast<float4*>(&E[8]) = pe4[2 * tc + 2];
        *reinterpret_cast<float4*>(&S[0]) = pos4[2 * tc];
        *reinterpret_cast<float4*>(&S[4]) = pos4[2 * tc + 1];
        *reinterpret_cast<float4*>(&S[8]) = pos4[2 * tc + 2];
        float4 wA = *reinterpret_cast<const float4*>(&ws[r][oc][0]);
        float4 wB = *reinterpret_cast<const float4*>(&ws[r][oc][4]);
#pragma unroll
        for (int j = 0; j < 8; j++) {
            acc[j] = fmaf(wA.x, E[j],     acc[j]);
            acc[j] = fmaf(wA.y, S[j + 1], acc[j]);
            acc[j] = fmaf(wA.z, E[j + 1], acc[j]);
            acc[j] = fmaf(wA.w, S[j + 2], acc[j]);
            acc[j] = fmaf(wB.x, E[j + 2], acc[j]);
            acc[j] = fmaf(wB.y, S[j + 3], acc[j]);
            acc[j] = fmaf(wB.z, E[j + 3], acc[j]);
        }
    }

    // ---- PDL sync: BN coefficients become valid only after finalize ----
#if __CUDA_ARCH__ >= 900
    cudaGridDependencySynchronize();
#endif
    {
        const float2 ab = g_ab[g * 4 + oc];
        float r0[8];
#pragma unroll
        for (int j = 0; j < 8; j++) {
            float v = fmaf(ab.x, acc[j], ab.y);
            r0[j] = (v >= 0.f) ? v : 0.01f * v;
        }
        int ob = ((b * Oo + g * 4 + oc) * FO + fo) * Tout + 8 * tc;
        *reinterpret_cast<float4*>(&out[ob])     = make_float4(r0[0], r0[1], r0[2], r0[3]);
        *reinterpret_cast<float4*>(&out[ob + 4]) = make_float4(r0[4], r0[5], r0[6], r0[7]);
    }
}

extern "C" void kernel_launch(void* const* d_in, const int* in_sizes, int n_in,
                              void* d_out, int out_size) {
    const float* x     = (const float*)d_in[0];
    const float* wgt   = (const float*)d_in[1];
    const float* gamma = (const float*)d_in[2];
    const float* beta  = (const float*)d_in[3];
    float* out = (float*)d_out;

    // Primary: stats (small resident footprint; triggers early on-device)
    stats_kernel<<<256, 256>>>(x, wgt);

    // Secondary launches with programmatic stream serialization (PDL).
    cudaLaunchAttribute attr[1];
    attr[0].id = cudaLaunchAttributeProgrammaticStreamSerialization;
    attr[0].val.programmaticStreamSerializationAllowed = 1;

    {
        cudaLaunchConfig_t cfg = {};
        cfg.gridDim  = dim3(1, 1, 1);
        cfg.blockDim = dim3(64, 1, 1);
        cfg.dynamicSmemBytes = 0;
        cfg.stream = 0;
        cfg.attrs = attr;
        cfg.numAttrs = 1;
        cudaLaunchKernelEx(&cfg, finalize_kernel, gamma, beta);
    }
    {
        cudaLaunchConfig_t cfg = {};
        cfg.gridDim  = dim3(2048, 1, 1);
        cfg.blockDim = dim3(128, 1, 1);
        cfg.dynamicSmemBytes = 0;
        cfg.stream = 0;
        cfg.attrs = attr;
        cfg.numAttrs = 1;
        cudaLaunchKernelEx(&cfg, conv_kernel, x, wgt, out);
    }
}

// round 16
// speedup vs baseline: 1.0917x; 1.0917x over previous
#include <cuda_runtime.h>

// Problem constants
#define Bn   2
#define Cc   64
#define Oo   64
#define Gg   16
#define Ee   128
#define Tin  512
#define Wk   7
#define Dd   4
#define Tout 256
#define FO   64
#define PER  264   // padded de-interleaved row length (floats)

// BN-stat partials: [o][j], j = b*32 + d*8 + fh  (64 slots)
__device__ float  g_part1[Oo][64];
__device__ float  g_part2[Oo][64];
__device__ float2 g_ab[Oo];           // {a, bias56}

// ---------------------------------------------------------------------------
// Stats kernel: 512 blocks x 256 threads, each block covers 2 chunks
// (chunk = (b,c,fh) unit; body identical to R8/R14-validated version).
// ~3.5 blocks/SM -> half the warp slots stay free for the PDL-launched conv.
// ---------------------------------------------------------------------------
__global__ __launch_bounds__(256) void stats_kernel(const float* __restrict__ x,
                                                    const float* __restrict__ wgt) {
#if __CUDA_ARCH__ >= 900
    cudaTriggerProgrammaticLaunchCompletion();
#endif
    __shared__ float s_p1[4], s_p2[4];

    const int tid  = threadIdx.x;
    const int warp = tid >> 5;
    const int lane = tid & 31;
    const int sl   = lane & 15;
    const int gidx = lane >> 4;
    const unsigned FULL = 0xffffffffu;

#pragma unroll 1
    for (int q = 0; q < 2; q++) {
        const int cid = blockIdx.x * 2 + q;     // 0..1023
        const int b   = cid >> 9;
        const int c   = (cid >> 3) & 63;
        const int fh  = cid & 7;
        const int f   = fh * 16 + warp * 2 + gidx;

        if (tid < 4) { s_p1[tid] = 0.f; s_p2[tid] = 0.f; }
        __syncthreads();

        const float4* row = reinterpret_cast<const float4*>(
            &x[((b * Cc + c) * Ee + f) * Tin]);

        float4 v[8];
#pragma unroll
        for (int k = 0; k < 8; k++) v[k] = row[sl + 16 * k];

        float se = 0.f, so = 0.f, se2 = 0.f, so2 = 0.f;
#pragma unroll
        for (int k = 0; k < 8; k++) {
            float4 qv = v[k];
            se += qv.x + qv.z;  so += qv.y + qv.w;
            se2 = fmaf(qv.x, qv.x, se2); se2 = fmaf(qv.z, qv.z, se2);
            so2 = fmaf(qv.y, qv.y, so2); so2 = fmaf(qv.w, qv.w, so2);
        }

        const int base = lane & ~15;
        float x0   = __shfl_sync(FULL, v[0].x, base);
        float x1   = __shfl_sync(FULL, v[0].y, base);
        float x509 = __shfl_sync(FULL, v[7].y, base + 15);
        float x510 = __shfl_sync(FULL, v[7].z, base + 15);
        float x511 = __shfl_sync(FULL, v[7].w, base + 15);

#pragma unroll
        for (int off = 1; off < 16; off <<= 1) {
            se  += __shfl_xor_sync(FULL, se,  off);
            so  += __shfl_xor_sync(FULL, so,  off);
            se2 += __shfl_xor_sync(FULL, se2, off);
            so2 += __shfl_xor_sync(FULL, so2, off);
        }

        float c1 = 0.f, c2 = 0.f;
        if (sl < 4) {
            float s1[7], s2[7];
            s1[0] = so - x509 - x511;  s2[0] = so2 - x509 * x509 - x511 * x511;
            s1[1] = se - x510;         s2[1] = se2 - x510 * x510;
            s1[2] = so - x511;         s2[2] = so2 - x511 * x511;
            s1[3] = se;                s2[3] = se2;
            s1[4] = so;                s2[4] = so2;
            s1[5] = se - x0;           s2[5] = se2 - x0 * x0;
            s1[6] = so - x1;           s2[6] = so2 - x1 * x1;

            const int g = c >> 2, d = c & 3;
            const int o = g * 4 + sl;
            const float* wp = &wgt[((o * Dd + d) * Ee + f) * Wk];
#pragma unroll
            for (int w = 0; w < 7; w++) {
                float wv = wp[w];
                c1 = fmaf(wv, s1[w], c1);
                c2 = fmaf(wv * wv, s2[w], c2);
            }
        }
        c1 += __shfl_xor_sync(FULL, c1, 16);
        c2 += __shfl_xor_sync(FULL, c2, 16);
        if (lane < 4) {
            atomicAdd(&s_p1[lane], c1);
            atomicAdd(&s_p2[lane], c2);
        }
        __syncthreads();
        if (tid < 4) {
            const int g = c >> 2, d = c & 3;
            const int j = b * 32 + d * 8 + fh;
            g_part1[g * 4 + tid][j] = s_p1[tid];
            g_part2[g * 4 + tid][j] = s_p2[tid];
        }
        __syncthreads();
    }
}

// ---------------------------------------------------------------------------
// Finalize: 1 block, 64 threads. Triggers at entry (lets conv co-schedule),
// then waits for stats completion before reducing partials.
// ---------------------------------------------------------------------------
__global__ __launch_bounds__(64) void finalize_kernel(const float* __restrict__ gamma,
                                                      const float* __restrict__ beta) {
#if __CUDA_ARCH__ >= 900
    cudaTriggerProgrammaticLaunchCompletion();
    cudaGridDependencySynchronize();
#endif
    const int o = threadIdx.x;
    const float4* p1v = reinterpret_cast<const float4*>(g_part1[o]);
    const float4* p2v = reinterpret_cast<const float4*>(g_part2[o]);
    float p1 = 0.f, p2 = 0.f;
#pragma unroll
    for (int k = 0; k < 16; k++) {
        float4 a = p1v[k], b = p2v[k];
        p1 += (a.x + a.y) + (a.z + a.w);
        p2 += (b.x + b.y) + (b.z + b.w);
    }
    const float M = 1835008.f;   // B*D*E*t*W
    float mean = p1 / M;
    float var  = p2 / M - mean * mean;
    float a    = gamma[o] * rsqrtf(var + 1e-5f);
    g_ab[o] = make_float2(a, 56.f * (beta[o] - mean * a));
}

// ---------------------------------------------------------------------------
// Fused conv + BN-affine + LeakyReLU (validated R5/R6 core). Block = (b,g,fo),
// 2048 blocks, 128 threads. Fill + FMA run before the PDL dependency sync;
// g_ab is read only in the epilogue, after cudaGridDependencySynchronize().
// ---------------------------------------------------------------------------
__global__ __launch_bounds__(128) void conv_kernel(const float* __restrict__ x,
                                                   const float* __restrict__ wgt,
                                                   float* __restrict__ out) {
    __shared__ alignas(16) float pe[8][PER];
    __shared__ alignas(16) float pos_[8][PER];
    __shared__ alignas(16) float ws[8][4][8];   // [w0..w6, 0]

    const int bid  = blockIdx.x;
    const int b    = bid >> 10;
    const int g    = (bid >> 6) & 15;
    const int fo   = bid & 63;
    const int tid  = threadIdx.x;
    const int lane = tid & 31;
    const int warp = tid >> 5;
    const int oc   = lane & 3;
    const int tc   = warp * 8 + (lane >> 2);   // 0..31; outputs t = 8tc..8tc+7

    // zero boundary slots {0,1,258..263} of each pe/pos_ row
    {
        int r  = tid >> 4;
        int s  = tid & 15;
        int ss = s & 7;
        int idx = (ss < 2) ? ss : (256 + ss);
        if (s < 8) pe[r][idx] = 0.f; else pos_[r][idx] = 0.f;
    }

    // de-interleaving fill
#pragma unroll
    for (int k = 0; k < 8; k++) {
        const int c = g * 4 + (k & 3);
        const int f = 2 * fo + (k >> 2);
        float4 v = reinterpret_cast<const float4*>(
            &x[((b * Cc + c) * Ee + f) * Tin])[tid];
        *reinterpret_cast<float2*>(&pe[k][2 * tid + 2])   = make_float2(v.y, v.w);
        *reinterpret_cast<float2*>(&pos_[k][2 * tid + 2]) = make_float2(v.x, v.z);
    }

    // weights
#pragma unroll
    for (int m = 0; m < 2; m++) {
        int j  = tid + 128 * m;
        int r  = j >> 5;
        int o2 = (j >> 3) & 3;
        int w  = j & 7;
        int d  = r & 3;
        int f2 = r >> 2;
        ws[r][o2][w] = (w < 7)
            ? wgt[(((g * 4 + o2) * Dd + d) * Ee + (2 * fo + f2)) * Wk + w] : 0.f;
    }
    __syncthreads();

    float acc[8];
#pragma unroll
    for (int j = 0; j < 8; j++) acc[j] = 0.f;

#pragma unroll
    for (int r = 0; r < 8; r++) {
        const float4* pe4  = reinterpret_cast<const float4*>(pe[r]);
        const float4* pos4 = reinterpret_cast<const float4*>(pos_[r]);
        float E[12], S[12];
        *reinterpret_cast<float4*>(&E[0]) = pe4[2 * tc];
        *reinterpret_cast<float4*>(&E[4]) = pe4[2 * tc + 1];
        *reinterpret_cast<float4*>(&E[8]) = pe4[2 * tc + 2];
        *reinterpret_cast<float4*>(&S[0]) = pos4[2 * tc];
        *reinterpret_cast<float4*>(&S[4]) = pos4[2 * tc + 1];
        *reinterpret_cast<float4*>(&S[8]) = pos4[2 * tc + 2];
        float4 wA = *reinterpret_cast<const float4*>(&ws[r][oc][0]);
        float4 wB = *reinterpret_cast<const float4*>(&ws[r][oc][4]);
#pragma unroll
        for (int j = 0; j < 8; j++) {
            acc[j] = fmaf(wA.x, E[j],     acc[j]);
            acc[j] = fmaf(wA.y, S[j + 1], acc[j]);
            acc[j] = fmaf(wA.z, E[j + 1], acc[j]);
            acc[j] = fmaf(wA.w, S[j + 2], acc[j]);
            acc[j] = fmaf(wB.x, E[j + 2], acc[j]);
            acc[j] = fmaf(wB.y, S[j + 3], acc[j]);
            acc[j] = fmaf(wB.z, E[j + 3], acc[j]);
        }
    }

    // ---- PDL sync: BN coefficients become valid only after finalize ----
#if __CUDA_ARCH__ >= 900
    cudaGridDependencySynchronize();
#endif
    {
        const float2 ab = g_ab[g * 4 + oc];
        float r0[8];
#pragma unroll
        for (int j = 0; j < 8; j++) {
            float v = fmaf(ab.x, acc[j], ab.y);
            r0[j] = (v >= 0.f) ? v : 0.01f * v;
        }
        int ob = ((b * Oo + g * 4 + oc) * FO + fo) * Tout + 8 * tc;
        *reinterpret_cast<float4*>(&out[ob])     = make_float4(r0[0], r0[1], r0[2], r0[3]);
        *reinterpret_cast<float4*>(&out[ob + 4]) = make_float4(r0[4], r0[5], r0[6], r0[7]);
    }
}

extern "C" void kernel_launch(void* const* d_in, const int* in_sizes, int n_in,
                              void* d_out, int out_size) {
    const float* x     = (const float*)d_in[0];
    const float* wgt   = (const float*)d_in[1];
    const float* gamma = (const float*)d_in[2];
    const float* beta  = (const float*)d_in[3];
    float* out = (float*)d_out;

    // Primary: stats (half-occupancy footprint; triggers early on-device)
    stats_kernel<<<512, 256>>>(x, wgt);

    // Secondary launches with programmatic stream serialization (PDL).
    cudaLaunchAttribute attr[1];
    attr[0].id = cudaLaunchAttributeProgrammaticStreamSerialization;
    attr[0].val.programmaticStreamSerializationAllowed = 1;

    {
        cudaLaunchConfig_t cfg = {};
        cfg.gridDim  = dim3(1, 1, 1);
        cfg.blockDim = dim3(64, 1, 1);
        cfg.dynamicSmemBytes = 0;
        cfg.stream = 0;
        cfg.attrs = attr;
        cfg.numAttrs = 1;
        cudaLaunchKernelEx(&cfg, finalize_kernel, gamma, beta);
    }
    {
        cudaLaunchConfig_t cfg = {};
        cfg.gridDim  = dim3(2048, 1, 1);
        cfg.blockDim = dim3(128, 1, 1);
        cfg.dynamicSmemBytes = 0;
        cfg.stream = 0;
        cfg.attrs = attr;
        cfg.numAttrs = 1;
        cudaLaunchKernelEx(&cfg, conv_kernel, x, wgt, out);
    }
}